// round 6
// baseline (speedup 1.0000x reference)
#include <cuda_runtime.h>

#define PI_F      3.14159265358979f
#define HALF_PI_F 1.57079632679490f

typedef unsigned long long u64;
struct P { u64 v; };

__device__ __forceinline__ P mkP(u64 x){ P r; r.v = x; return r; }
__device__ __forceinline__ P pack2(float lo, float hi){
    P r; asm("mov.b64 %0,{%1,%2};" : "=l"(r.v) : "f"(lo), "f"(hi)); return r;
}
__device__ __forceinline__ P dupP(float v){
    P r; asm("mov.b64 %0,{%1,%1};" : "=l"(r.v) : "f"(v)); return r;
}
__device__ __forceinline__ void unpack2(P a, float& lo, float& hi){
    asm("mov.b64 {%0,%1},%2;" : "=f"(lo), "=f"(hi) : "l"(a.v));
}
__device__ __forceinline__ P fma2(P a, P b, P c){
    P r; asm("fma.rn.f32x2 %0,%1,%2,%3;" : "=l"(r.v) : "l"(a.v), "l"(b.v), "l"(c.v)); return r;
}
__device__ __forceinline__ P negP(P a){ P r; r.v = a.v ^ 0x8000000080000000ULL; return r; }

#define K_ZERO (mkP(0ULL))
#define K_ONE  (mkP(0x3F8000003F800000ULL))
#define K_NEG1 (mkP(0xBF800000BF800000ULL))

// packed mul/add/sub expressed as FFMA2 (the only packed fp32 SASS op)
__device__ __forceinline__ P mul2(P a, P b){ return fma2(a, b, K_ZERO); }
__device__ __forceinline__ P add2(P a, P b){ return fma2(a, K_ONE, b); }
__device__ __forceinline__ P sub2(P a, P b){ return fma2(b, K_NEG1, a); }

// (ar+i*ai)*(br+i*bi) -> (rr, ri)
__device__ __forceinline__ void cmul(P ar_, P ai_, P br_, P bi_, P& rr, P& ri){
    rr = fma2(mul2(ai_, bi_), K_NEG1, mul2(ar_, br_));
    ri = fma2(ar_, bi_, mul2(ai_, br_));
}

// shared layout (floats). MLP weights TRANSPOSED, adjacent-neuron pairs, NOT duplicated.
#define OFF_W1   0      // 64
#define OFF_B1   64     // 16
#define OFF_W2   80     // 512
#define OFF_B2   592    // 32
#define OFF_W3   624    // 512
#define OFF_B3   1136   // 16
#define OFF_TRIG 1152   // 32 (pair-duplicated trig for batch-packed use)
#define SW_TOTAL 1184

#define BLK 128

__global__ __launch_bounds__(BLK, 5) void hqae_kernel(
    const float* __restrict__ x,  const float* __restrict__ qw,
    const float* __restrict__ W1, const float* __restrict__ b1,
    const float* __restrict__ W2, const float* __restrict__ b2,
    const float* __restrict__ W3, const float* __restrict__ b3,
    float* __restrict__ out, int n)
{
    __shared__ __align__(16) float sw[SW_TOTAL];
    const int tid = threadIdx.x;

    for (int i = tid; i < 64;  i += BLK){ int k = i >> 4, j = i & 15; sw[OFF_W1 + i] = W1[j*4 + k]; }
    for (int i = tid; i < 512; i += BLK){ int k = i >> 5, j = i & 31; sw[OFF_W2 + i] = W2[j*16 + k]; }
    for (int i = tid; i < 512; i += BLK){ int k = i >> 4, j = i & 15; sw[OFF_W3 + i] = W3[j*32 + k]; }
    for (int i = tid; i < 16;  i += BLK) sw[OFF_B1 + i] = b1[i];
    for (int i = tid; i < 32;  i += BLK) sw[OFF_B2 + i] = b2[i];
    for (int i = tid; i < 16;  i += BLK) sw[OFF_B3 + i] = b3[i];
    if (tid < 4) {
        float s, c;
        __sincosf(qw[2*tid] * 0.5f, &s, &c);   // RY half-angle
        sw[OFF_TRIG + tid*8 + 0] = c; sw[OFF_TRIG + tid*8 + 1] = c;
        sw[OFF_TRIG + tid*8 + 2] = s; sw[OFF_TRIG + tid*8 + 3] = s;
        __sincosf(qw[2*tid + 1], &s, &c);      // RZ full angle (global-phase trick)
        sw[OFF_TRIG + tid*8 + 4] = c; sw[OFF_TRIG + tid*8 + 5] = c;
        sw[OFF_TRIG + tid*8 + 6] = s; sw[OFF_TRIG + tid*8 + 7] = s;
    }
    __syncthreads();

    const int half = n >> 1;                   // pair (b, b+half)
    const int b0 = blockIdx.x * BLK + tid;
    if (b0 >= half) return;
    const int b1i = b0 + half;

    // ---- load x rows for both elements ----
    const float4* xv0 = (const float4*)(x + (size_t)b0  * 16);
    const float4* xv1 = (const float4*)(x + (size_t)b1i * 16);
    float4 a0 = xv0[0], a1 = xv0[1];
    float4 c0v = xv1[0], c1v = xv1[1];
    float xA[8] = {a0.x, a0.y, a0.z, a0.w, a1.x, a1.y, a1.z, a1.w};
    float xB[8] = {c0v.x, c0v.y, c0v.z, c0v.w, c1v.x, c1v.y, c1v.z, c1v.w};

    // ---- layer 1: per-qubit product vectors (amp0 real = cq, amp1 = ur+i*ui) ----
    P cq[4], urq[4], uiq[4];
#pragma unroll
    for (int i = 0; i < 4; i++) {
        float sA, cA, sB, cB;
        __sincosf(xA[i] * HALF_PI_F, &sA, &cA);
        __sincosf(xB[i] * HALF_PI_F, &sB, &cB);
        float psA, pcA, psB, pcB;
        __sincosf(xA[i+4] * PI_F, &psA, &pcA);
        __sincosf(xB[i+4] * PI_F, &psB, &pcB);
        cq[i] = pack2(cA, cB);
        P s2  = pack2(sA, sB);
        urq[i] = mul2(s2, pack2(pcA, pcB));
        uiq[i] = mul2(s2, pack2(psA, psB));
    }

    // ---- tensor product (amp-0 real chain explicit) ----
    P t2r[4], t2i[4];
    t2r[0] = mul2(cq[0], cq[1]);
    t2r[1] = mul2(cq[0], urq[1]); t2i[1] = mul2(cq[0], uiq[1]);
    t2r[2] = mul2(urq[0], cq[1]); t2i[2] = mul2(uiq[0], cq[1]);
    cmul(urq[0], uiq[0], urq[1], uiq[1], t2r[3], t2i[3]);

    P t3r[8], t3i[8];
    t3r[0] = mul2(t2r[0], cq[2]);
    t3r[1] = mul2(t2r[0], urq[2]); t3i[1] = mul2(t2r[0], uiq[2]);
#pragma unroll
    for (int k = 1; k < 4; k++) {
        t3r[2*k] = mul2(t2r[k], cq[2]);
        t3i[2*k] = mul2(t2i[k], cq[2]);
        cmul(t2r[k], t2i[k], urq[2], uiq[2], t3r[2*k+1], t3i[2*k+1]);
    }

    P ar[16], ai[16];
    ar[0] = mul2(t3r[0], cq[3]); ai[0] = K_ZERO;
    ar[1] = mul2(t3r[0], urq[3]); ai[1] = mul2(t3r[0], uiq[3]);
#pragma unroll
    for (int k = 1; k < 8; k++) {
        ar[2*k] = mul2(t3r[k], cq[3]);
        ai[2*k] = mul2(t3i[k], cq[3]);
        cmul(t3r[k], t3i[k], urq[3], uiq[3], ar[2*k+1], ai[2*k+1]);
    }

    // ---- CNOT chains: register relabelings (wire0 = bit value 8) ----
#define SWAMP(p, q) { P t_ = ar[p]; ar[p] = ar[q]; ar[q] = t_; \
                      t_ = ai[p]; ai[p] = ai[q]; ai[q] = t_; }
    SWAMP(8,12) SWAMP(9,13) SWAMP(10,14) SWAMP(11,15)
    SWAMP(4,6)  SWAMP(5,7)  SWAMP(12,14) SWAMP(13,15)
    SWAMP(2,3)  SWAMP(6,7)  SWAMP(10,11) SWAMP(14,15)

    // ---- variational layer: RY then RZ per qubit (batch-packed) ----
    const ulonglong2* trp = (const ulonglong2*)(sw + OFF_TRIG);
#pragma unroll
    for (int i = 0; i < 4; i++) {
        ulonglong2 u0 = trp[i*2], u1 = trp[i*2+1];
        P cy = mkP(u0.x), sy = mkP(u0.y), zc = mkP(u1.x), zs = mkP(u1.y);
        P syn = negP(sy), zsn = negP(zs);
        const int m = 8 >> i;
#pragma unroll
        for (int k = 0; k < 16; k++) {
            if (k & m) continue;
            const int k1 = k | m;
            P a0r = ar[k],  a0i = ai[k];
            P a1r = ar[k1], a1i = ai[k1];
            P n1r = fma2(sy, a0r, mul2(cy, a1r));
            P n1i = fma2(sy, a0i, mul2(cy, a1i));
            ar[k]  = fma2(syn, a1r, mul2(cy, a0r));
            ai[k]  = fma2(syn, a1i, mul2(cy, a0i));
            ar[k1] = fma2(zsn, n1i, mul2(zc, n1r));
            ai[k1] = fma2(zs,  n1r, mul2(zc, n1i));
        }
    }

    // ---- second CNOT chain ----
    SWAMP(8,12) SWAMP(9,13) SWAMP(10,14) SWAMP(11,15)
    SWAMP(4,6)  SWAMP(5,7)  SWAMP(12,14) SWAMP(13,15)
    SWAMP(2,3)  SWAMP(6,7)  SWAMP(10,11) SWAMP(14,15)

    // ---- probs ----
    P p[16];
#pragma unroll
    for (int k = 0; k < 16; k++) p[k] = fma2(ar[k], ar[k], mul2(ai[k], ai[k]));

    // ---- PauliZ expvals via shared Walsh partial sums (40 packed ops vs 60) ----
    float zA[4], zB[4];
    {
        P s0[8], d0sum;                      // level 1: over bit0 (wire 3)
        {
            P d0[8];
#pragma unroll
            for (int k = 0; k < 8; k++) {
                s0[k] = add2(p[2*k], p[2*k+1]);
                d0[k] = sub2(p[2*k], p[2*k+1]);
            }
            P t01 = add2(d0[0], d0[1]), t23 = add2(d0[2], d0[3]);
            P t45 = add2(d0[4], d0[5]), t67 = add2(d0[6], d0[7]);
            d0sum = add2(add2(t01, t23), add2(t45, t67));
        }
        unpack2(d0sum, zA[3], zB[3]);

        P s1[4];                             // level 2: over bit1 (wire 2)
        {
            P d1[4];
#pragma unroll
            for (int k = 0; k < 4; k++) {
                s1[k] = add2(s0[2*k], s0[2*k+1]);
                d1[k] = sub2(s0[2*k], s0[2*k+1]);
            }
            P z2p = add2(add2(d1[0], d1[1]), add2(d1[2], d1[3]));
            unpack2(z2p, zA[2], zB[2]);
        }
        P s2a = add2(s1[0], s1[1]), s2b = add2(s1[2], s1[3]);   // level 3: bit2 (wire 1)
        P z1p = add2(sub2(s1[0], s1[1]), sub2(s1[2], s1[3]));
        unpack2(z1p, zA[1], zB[1]);
        P z0p = sub2(s2a, s2b);                                  // level 4: bit3 (wire 0)
        unpack2(z0p, zA[0], zB[0]);
    }

    // ================= MLP: neuron-pair packing, weight loads shared A/B =================
    const P* B1p = (const P*)(sw + OFF_B1);
    const P* B2p = (const P*)(sw + OFF_B2);
    const P* B3p = (const P*)(sw + OFF_B3);

    // ---- layer 1: 4 -> 16 ----
    P aA1[8], aB1[8];
#pragma unroll
    for (int jp = 0; jp < 8; jp++) { P bb = B1p[jp]; aA1[jp] = bb; aB1[jp] = bb; }
#pragma unroll
    for (int k = 0; k < 4; k++) {
        P dA = dupP(zA[k]), dB = dupP(zB[k]);
        const ulonglong2* row = (const ulonglong2*)(sw + OFF_W1 + k*16);
#pragma unroll
        for (int q = 0; q < 4; q++) {
            ulonglong2 u = row[q];
            P w0 = mkP(u.x), w1 = mkP(u.y);
            aA1[2*q]   = fma2(w0, dA, aA1[2*q]);
            aA1[2*q+1] = fma2(w1, dA, aA1[2*q+1]);
            aB1[2*q]   = fma2(w0, dB, aB1[2*q]);
            aB1[2*q+1] = fma2(w1, dB, aB1[2*q+1]);
        }
    }
    float h1A[16], h1B[16];
#pragma unroll
    for (int jp = 0; jp < 8; jp++) {
        float lo, hi;
        unpack2(aA1[jp], lo, hi);
        h1A[2*jp] = fmaxf(lo, 0.0f); h1A[2*jp+1] = fmaxf(hi, 0.0f);
        unpack2(aB1[jp], lo, hi);
        h1B[2*jp] = fmaxf(lo, 0.0f); h1B[2*jp+1] = fmaxf(hi, 0.0f);
    }

    // ---- layer 2: 16 -> 32 ----
    P aA2[16], aB2[16];
#pragma unroll
    for (int jp = 0; jp < 16; jp++) { P bb = B2p[jp]; aA2[jp] = bb; aB2[jp] = bb; }
#pragma unroll
    for (int k = 0; k < 16; k++) {
        P dA = dupP(h1A[k]), dB = dupP(h1B[k]);
        const ulonglong2* row = (const ulonglong2*)(sw + OFF_W2 + k*32);
#pragma unroll
        for (int q = 0; q < 8; q++) {
            ulonglong2 u = row[q];
            P w0 = mkP(u.x), w1 = mkP(u.y);
            aA2[2*q]   = fma2(w0, dA, aA2[2*q]);
            aA2[2*q+1] = fma2(w1, dA, aA2[2*q+1]);
            aB2[2*q]   = fma2(w0, dB, aB2[2*q]);
            aB2[2*q+1] = fma2(w1, dB, aB2[2*q+1]);
        }
    }
    float h2A[32], h2B[32];
#pragma unroll
    for (int jp = 0; jp < 16; jp++) {
        float lo, hi;
        unpack2(aA2[jp], lo, hi);
        h2A[2*jp] = fmaxf(lo, 0.0f); h2A[2*jp+1] = fmaxf(hi, 0.0f);
        unpack2(aB2[jp], lo, hi);
        h2B[2*jp] = fmaxf(lo, 0.0f); h2B[2*jp+1] = fmaxf(hi, 0.0f);
    }

    // ---- layer 3: 32 -> 16 ----
    P aA3[8], aB3[8];
#pragma unroll
    for (int jp = 0; jp < 8; jp++) { P bb = B3p[jp]; aA3[jp] = bb; aB3[jp] = bb; }
#pragma unroll
    for (int k = 0; k < 32; k++) {
        P dA = dupP(h2A[k]), dB = dupP(h2B[k]);
        const ulonglong2* row = (const ulonglong2*)(sw + OFF_W3 + k*16);
#pragma unroll
        for (int q = 0; q < 4; q++) {
            ulonglong2 u = row[q];
            P w0 = mkP(u.x), w1 = mkP(u.y);
            aA3[2*q]   = fma2(w0, dA, aA3[2*q]);
            aA3[2*q+1] = fma2(w1, dA, aA3[2*q+1]);
            aB3[2*q]   = fma2(w0, dB, aB3[2*q]);
            aB3[2*q+1] = fma2(w1, dB, aB3[2*q+1]);
        }
    }

    // ---- store: acc pairs are already {o_2j, o_2j+1} in memory order ----
    float* o0 = out + (size_t)b0  * 16;
    float* o1 = out + (size_t)b1i * 16;
#pragma unroll
    for (int g = 0; g < 4; g++) {
        float4 v;
        unpack2(aA3[2*g],   v.x, v.y);
        unpack2(aA3[2*g+1], v.z, v.w);
        ((float4*)o0)[g] = v;
        unpack2(aB3[2*g],   v.x, v.y);
        unpack2(aB3[2*g+1], v.z, v.w);
        ((float4*)o1)[g] = v;
    }
}

extern "C" void kernel_launch(void* const* d_in, const int* in_sizes, int n_in,
                              void* d_out, int out_size)
{
    const float* x  = (const float*)d_in[0];
    const float* qw = (const float*)d_in[1];
    const float* W1 = (const float*)d_in[2];
    const float* b1 = (const float*)d_in[3];
    const float* W2 = (const float*)d_in[4];
    const float* b2 = (const float*)d_in[5];
    const float* W3 = (const float*)d_in[6];
    const float* b3 = (const float*)d_in[7];
    float* out = (float*)d_out;

    const int n = in_sizes[0] / 16;           // B (even)
    const int half = n >> 1;
    const int blocks = (half + BLK - 1) / BLK;
    hqae_kernel<<<blocks, BLK>>>(x, qw, W1, b1, W2, b2, W3, b3, out, n);
}

// round 7
// speedup vs baseline: 1.1341x; 1.1341x over previous
#include <cuda_runtime.h>

#define PI_F      3.14159265358979f
#define HALF_PI_F 1.57079632679490f

typedef unsigned long long u64;
struct P { u64 v; };

__device__ __forceinline__ P mkP(u64 x){ P r; r.v = x; return r; }
__device__ __forceinline__ P pack2(float lo, float hi){
    P r; asm("mov.b64 %0,{%1,%2};" : "=l"(r.v) : "f"(lo), "f"(hi)); return r;
}
__device__ __forceinline__ P dupP(float v){
    P r; asm("mov.b64 %0,{%1,%1};" : "=l"(r.v) : "f"(v)); return r;
}
__device__ __forceinline__ void unpack2(P a, float& lo, float& hi){
    asm("mov.b64 {%0,%1},%2;" : "=f"(lo), "=f"(hi) : "l"(a.v));
}
__device__ __forceinline__ P fma2(P a, P b, P c){
    P r; asm("fma.rn.f32x2 %0,%1,%2,%3;" : "=l"(r.v) : "l"(a.v), "l"(b.v), "l"(c.v)); return r;
}
__device__ __forceinline__ P negP(P a){ P r; r.v = a.v ^ 0x8000000080000000ULL; return r; }

#define K_ZERO (mkP(0ULL))
#define K_ONE  (mkP(0x3F8000003F800000ULL))
#define K_NEG1 (mkP(0xBF800000BF800000ULL))

// packed mul/add/sub expressed as FFMA2 (the only packed fp32 SASS op)
__device__ __forceinline__ P mul2(P a, P b){ return fma2(a, b, K_ZERO); }
__device__ __forceinline__ P add2(P a, P b){ return fma2(a, K_ONE, b); }
__device__ __forceinline__ P sub2(P a, P b){ return fma2(b, K_NEG1, a); }

// (ar+i*ai)*(br+i*bi) -> (rr, ri)
__device__ __forceinline__ void cmul(P ar_, P ai_, P br_, P bi_, P& rr, P& ri){
    rr = fma2(mul2(ai_, bi_), K_NEG1, mul2(ar_, br_));
    ri = fma2(ar_, bi_, mul2(ai_, br_));
}

// shared layout (floats). MLP weights TRANSPOSED, adjacent-neuron pairs, NOT duplicated.
#define OFF_W1   0      // 64
#define OFF_B1   64     // 16
#define OFF_W2   80     // 512
#define OFF_B2   592    // 32
#define OFF_W3   624    // 512
#define OFF_B3   1136   // 16
#define OFF_TRIG 1152   // 16 (pair-duplicated RY trig only; variational RZ dropped)
#define SW_TOTAL 1168

#define BLK 256

__global__ __launch_bounds__(BLK, 2) void hqae_kernel(
    const float* __restrict__ x,  const float* __restrict__ qw,
    const float* __restrict__ W1, const float* __restrict__ b1,
    const float* __restrict__ W2, const float* __restrict__ b2,
    const float* __restrict__ W3, const float* __restrict__ b3,
    float* __restrict__ out, int n)
{
    __shared__ __align__(16) float sw[SW_TOTAL];
    const int tid = threadIdx.x;

    for (int i = tid; i < 64;  i += BLK){ int k = i >> 4, j = i & 15; sw[OFF_W1 + i] = W1[j*4 + k]; }
    for (int i = tid; i < 512; i += BLK){ int k = i >> 5, j = i & 31; sw[OFF_W2 + i] = W2[j*16 + k]; }
    for (int i = tid; i < 512; i += BLK){ int k = i >> 4, j = i & 15; sw[OFF_W3 + i] = W3[j*32 + k]; }
    for (int i = tid; i < 16;  i += BLK) sw[OFF_B1 + i] = b1[i];
    for (int i = tid; i < 32;  i += BLK) sw[OFF_B2 + i] = b2[i];
    for (int i = tid; i < 16;  i += BLK) sw[OFF_B3 + i] = b3[i];
    if (tid < 4) {
        // Variational RZ gates are diagonal unit-phase; they commute through the
        // final CNOT permutation and vanish under |amp|^2 -> dropped entirely.
        float s, c;
        __sincosf(qw[2*tid] * 0.5f, &s, &c);   // RY half-angle only
        sw[OFF_TRIG + tid*4 + 0] = c; sw[OFF_TRIG + tid*4 + 1] = c;
        sw[OFF_TRIG + tid*4 + 2] = s; sw[OFF_TRIG + tid*4 + 3] = s;
    }
    __syncthreads();

    const int half = n >> 1;                   // pair (b, b+half)
    const int b0 = blockIdx.x * BLK + tid;
    if (b0 >= half) return;
    const int b1i = b0 + half;

    // ---- load x rows for both elements ----
    const float4* xv0 = (const float4*)(x + (size_t)b0  * 16);
    const float4* xv1 = (const float4*)(x + (size_t)b1i * 16);
    float4 a0 = xv0[0], a1 = xv0[1];
    float4 c0v = xv1[0], c1v = xv1[1];
    float xA[8] = {a0.x, a0.y, a0.z, a0.w, a1.x, a1.y, a1.z, a1.w};
    float xB[8] = {c0v.x, c0v.y, c0v.z, c0v.w, c1v.x, c1v.y, c1v.z, c1v.w};

    // ---- layer 1: per-qubit product vectors (amp0 real = cq, amp1 = ur+i*ui) ----
    P cq[4], urq[4], uiq[4];
#pragma unroll
    for (int i = 0; i < 4; i++) {
        float sA, cA, sB, cB;
        __sincosf(xA[i] * HALF_PI_F, &sA, &cA);
        __sincosf(xB[i] * HALF_PI_F, &sB, &cB);
        float psA, pcA, psB, pcB;
        __sincosf(xA[i+4] * PI_F, &psA, &pcA);
        __sincosf(xB[i+4] * PI_F, &psB, &pcB);
        cq[i] = pack2(cA, cB);
        P s2  = pack2(sA, sB);
        urq[i] = mul2(s2, pack2(pcA, pcB));
        uiq[i] = mul2(s2, pack2(psA, psB));
    }

    // ---- tensor product (amp-0 real chain explicit) ----
    P t2r[4], t2i[4];
    t2r[0] = mul2(cq[0], cq[1]);
    t2r[1] = mul2(cq[0], urq[1]); t2i[1] = mul2(cq[0], uiq[1]);
    t2r[2] = mul2(urq[0], cq[1]); t2i[2] = mul2(uiq[0], cq[1]);
    cmul(urq[0], uiq[0], urq[1], uiq[1], t2r[3], t2i[3]);

    P t3r[8], t3i[8];
    t3r[0] = mul2(t2r[0], cq[2]);
    t3r[1] = mul2(t2r[0], urq[2]); t3i[1] = mul2(t2r[0], uiq[2]);
#pragma unroll
    for (int k = 1; k < 4; k++) {
        t3r[2*k] = mul2(t2r[k], cq[2]);
        t3i[2*k] = mul2(t2i[k], cq[2]);
        cmul(t2r[k], t2i[k], urq[2], uiq[2], t3r[2*k+1], t3i[2*k+1]);
    }

    P ar[16], ai[16];
    ar[0] = mul2(t3r[0], cq[3]); ai[0] = K_ZERO;
    ar[1] = mul2(t3r[0], urq[3]); ai[1] = mul2(t3r[0], uiq[3]);
#pragma unroll
    for (int k = 1; k < 8; k++) {
        ar[2*k] = mul2(t3r[k], cq[3]);
        ai[2*k] = mul2(t3i[k], cq[3]);
        cmul(t3r[k], t3i[k], urq[3], uiq[3], ar[2*k+1], ai[2*k+1]);
    }

    // ---- CNOT chains: register relabelings (wire0 = bit value 8) ----
#define SWAMP(p, q) { P t_ = ar[p]; ar[p] = ar[q]; ar[q] = t_; \
                      t_ = ai[p]; ai[p] = ai[q]; ai[q] = t_; }
    SWAMP(8,12) SWAMP(9,13) SWAMP(10,14) SWAMP(11,15)
    SWAMP(4,6)  SWAMP(5,7)  SWAMP(12,14) SWAMP(13,15)
    SWAMP(2,3)  SWAMP(6,7)  SWAMP(10,11) SWAMP(14,15)

    // ---- variational layer: RY only (RZ dropped — see init comment) ----
    const P* trp = (const P*)(sw + OFF_TRIG);
#pragma unroll
    for (int i = 0; i < 4; i++) {
        ulonglong2 u = ((const ulonglong2*)trp)[i];
        P cy = mkP(u.x), sy = mkP(u.y);
        P syn = negP(sy);
        const int m = 8 >> i;
#pragma unroll
        for (int k = 0; k < 16; k++) {
            if (k & m) continue;
            const int k1 = k | m;
            P a0r = ar[k],  a0i = ai[k];
            P a1r = ar[k1], a1i = ai[k1];
            ar[k1] = fma2(sy, a0r, mul2(cy, a1r));
            ai[k1] = fma2(sy, a0i, mul2(cy, a1i));
            ar[k]  = fma2(syn, a1r, mul2(cy, a0r));
            ai[k]  = fma2(syn, a1i, mul2(cy, a0i));
        }
    }

    // ---- second CNOT chain ----
    SWAMP(8,12) SWAMP(9,13) SWAMP(10,14) SWAMP(11,15)
    SWAMP(4,6)  SWAMP(5,7)  SWAMP(12,14) SWAMP(13,15)
    SWAMP(2,3)  SWAMP(6,7)  SWAMP(10,11) SWAMP(14,15)

    // ---- probs ----
    P p[16];
#pragma unroll
    for (int k = 0; k < 16; k++) p[k] = fma2(ar[k], ar[k], mul2(ai[k], ai[k]));

    // ---- PauliZ expvals via shared Walsh partial sums ----
    float zA[4], zB[4];
    {
        P s0[8], d0sum;                      // level 1: over bit0 (wire 3)
        {
            P d0[8];
#pragma unroll
            for (int k = 0; k < 8; k++) {
                s0[k] = add2(p[2*k], p[2*k+1]);
                d0[k] = sub2(p[2*k], p[2*k+1]);
            }
            P t01 = add2(d0[0], d0[1]), t23 = add2(d0[2], d0[3]);
            P t45 = add2(d0[4], d0[5]), t67 = add2(d0[6], d0[7]);
            d0sum = add2(add2(t01, t23), add2(t45, t67));
        }
        unpack2(d0sum, zA[3], zB[3]);

        P s1[4];                             // level 2: over bit1 (wire 2)
        {
            P d1[4];
#pragma unroll
            for (int k = 0; k < 4; k++) {
                s1[k] = add2(s0[2*k], s0[2*k+1]);
                d1[k] = sub2(s0[2*k], s0[2*k+1]);
            }
            P z2p = add2(add2(d1[0], d1[1]), add2(d1[2], d1[3]));
            unpack2(z2p, zA[2], zB[2]);
        }
        P s2a = add2(s1[0], s1[1]), s2b = add2(s1[2], s1[3]);   // level 3: bit2 (wire 1)
        P z1p = add2(sub2(s1[0], s1[1]), sub2(s1[2], s1[3]));
        unpack2(z1p, zA[1], zB[1]);
        P z0p = sub2(s2a, s2b);                                  // level 4: bit3 (wire 0)
        unpack2(z0p, zA[0], zB[0]);
    }

    // ================= MLP: neuron-pair packing, weight loads shared A/B =================
    const P* B1p = (const P*)(sw + OFF_B1);
    const P* B2p = (const P*)(sw + OFF_B2);
    const P* B3p = (const P*)(sw + OFF_B3);

    // ---- layer 1: 4 -> 16 ----
    P aA1[8], aB1[8];
#pragma unroll
    for (int jp = 0; jp < 8; jp++) { P bb = B1p[jp]; aA1[jp] = bb; aB1[jp] = bb; }
#pragma unroll
    for (int k = 0; k < 4; k++) {
        P dA = dupP(zA[k]), dB = dupP(zB[k]);
        const ulonglong2* row = (const ulonglong2*)(sw + OFF_W1 + k*16);
#pragma unroll
        for (int q = 0; q < 4; q++) {
            ulonglong2 u = row[q];
            P w0 = mkP(u.x), w1 = mkP(u.y);
            aA1[2*q]   = fma2(w0, dA, aA1[2*q]);
            aA1[2*q+1] = fma2(w1, dA, aA1[2*q+1]);
            aB1[2*q]   = fma2(w0, dB, aB1[2*q]);
            aB1[2*q+1] = fma2(w1, dB, aB1[2*q+1]);
        }
    }
    float h1A[16], h1B[16];
#pragma unroll
    for (int jp = 0; jp < 8; jp++) {
        float lo, hi;
        unpack2(aA1[jp], lo, hi);
        h1A[2*jp] = fmaxf(lo, 0.0f); h1A[2*jp+1] = fmaxf(hi, 0.0f);
        unpack2(aB1[jp], lo, hi);
        h1B[2*jp] = fmaxf(lo, 0.0f); h1B[2*jp+1] = fmaxf(hi, 0.0f);
    }

    // ---- layer 2: 16 -> 32 ----
    P aA2[16], aB2[16];
#pragma unroll
    for (int jp = 0; jp < 16; jp++) { P bb = B2p[jp]; aA2[jp] = bb; aB2[jp] = bb; }
#pragma unroll
    for (int k = 0; k < 16; k++) {
        P dA = dupP(h1A[k]), dB = dupP(h1B[k]);
        const ulonglong2* row = (const ulonglong2*)(sw + OFF_W2 + k*32);
#pragma unroll
        for (int q = 0; q < 8; q++) {
            ulonglong2 u = row[q];
            P w0 = mkP(u.x), w1 = mkP(u.y);
            aA2[2*q]   = fma2(w0, dA, aA2[2*q]);
            aA2[2*q+1] = fma2(w1, dA, aA2[2*q+1]);
            aB2[2*q]   = fma2(w0, dB, aB2[2*q]);
            aB2[2*q+1] = fma2(w1, dB, aB2[2*q+1]);
        }
    }
    float h2A[32], h2B[32];
#pragma unroll
    for (int jp = 0; jp < 16; jp++) {
        float lo, hi;
        unpack2(aA2[jp], lo, hi);
        h2A[2*jp] = fmaxf(lo, 0.0f); h2A[2*jp+1] = fmaxf(hi, 0.0f);
        unpack2(aB2[jp], lo, hi);
        h2B[2*jp] = fmaxf(lo, 0.0f); h2B[2*jp+1] = fmaxf(hi, 0.0f);
    }

    // ---- layer 3: 32 -> 16 ----
    P aA3[8], aB3[8];
#pragma unroll
    for (int jp = 0; jp < 8; jp++) { P bb = B3p[jp]; aA3[jp] = bb; aB3[jp] = bb; }
#pragma unroll
    for (int k = 0; k < 32; k++) {
        P dA = dupP(h2A[k]), dB = dupP(h2B[k]);
        const ulonglong2* row = (const ulonglong2*)(sw + OFF_W3 + k*16);
#pragma unroll
        for (int q = 0; q < 4; q++) {
            ulonglong2 u = row[q];
            P w0 = mkP(u.x), w1 = mkP(u.y);
            aA3[2*q]   = fma2(w0, dA, aA3[2*q]);
            aA3[2*q+1] = fma2(w1, dA, aA3[2*q+1]);
            aB3[2*q]   = fma2(w0, dB, aB3[2*q]);
            aB3[2*q+1] = fma2(w1, dB, aB3[2*q+1]);
        }
    }

    // ---- store: acc pairs are already {o_2j, o_2j+1} in memory order ----
    float* o0 = out + (size_t)b0  * 16;
    float* o1 = out + (size_t)b1i * 16;
#pragma unroll
    for (int g = 0; g < 4; g++) {
        float4 v;
        unpack2(aA3[2*g],   v.x, v.y);
        unpack2(aA3[2*g+1], v.z, v.w);
        ((float4*)o0)[g] = v;
        unpack2(aB3[2*g],   v.x, v.y);
        unpack2(aB3[2*g+1], v.z, v.w);
        ((float4*)o1)[g] = v;
    }
}

extern "C" void kernel_launch(void* const* d_in, const int* in_sizes, int n_in,
                              void* d_out, int out_size)
{
    const float* x  = (const float*)d_in[0];
    const float* qw = (const float*)d_in[1];
    const float* W1 = (const float*)d_in[2];
    const float* b1 = (const float*)d_in[3];
    const float* W2 = (const float*)d_in[4];
    const float* b2 = (const float*)d_in[5];
    const float* W3 = (const float*)d_in[6];
    const float* b3 = (const float*)d_in[7];
    float* out = (float*)d_out;

    const int n = in_sizes[0] / 16;           // B (even)
    const int half = n >> 1;
    const int blocks = (half + BLK - 1) / BLK;
    hqae_kernel<<<blocks, BLK>>>(x, qw, W1, b1, W2, b2, W3, b3, out, n);
}

// round 8
// speedup vs baseline: 1.2401x; 1.0935x over previous
#include <cuda_runtime.h>

#define PI_F 3.14159265358979f

typedef unsigned long long u64;
struct P { u64 v; };

__device__ __forceinline__ P mkP(u64 x){ P r; r.v = x; return r; }
__device__ __forceinline__ P pack2(float lo, float hi){
    P r; asm("mov.b64 %0,{%1,%2};" : "=l"(r.v) : "f"(lo), "f"(hi)); return r;
}
__device__ __forceinline__ P dupP(float v){
    P r; asm("mov.b64 %0,{%1,%1};" : "=l"(r.v) : "f"(v)); return r;
}
__device__ __forceinline__ void unpack2(P a, float& lo, float& hi){
    asm("mov.b64 {%0,%1},%2;" : "=f"(lo), "=f"(hi) : "l"(a.v));
}
__device__ __forceinline__ P fma2(P a, P b, P c){
    P r; asm("fma.rn.f32x2 %0,%1,%2,%3;" : "=l"(r.v) : "l"(a.v), "l"(b.v), "l"(c.v)); return r;
}
#define K_ZERO (mkP(0ULL))
__device__ __forceinline__ P mul2(P a, P b){ return fma2(a, b, K_ZERO); }

// shared layout (floats). MLP weights TRANSPOSED, adjacent-neuron pairs.
#define OFF_W1   0      // 64
#define OFF_B1   64     // 16
#define OFF_W2   80     // 512
#define OFF_B2   592    // 32
#define OFF_W3   624    // 512
#define OFF_B3   1136   // 16
#define OFF_C    1152   // 60 (30 pair-duplicated Heisenberg coefficients)
#define SW_TOTAL 1216

#define BLK 256

__global__ __launch_bounds__(BLK, 2) void hqae_kernel(
    const float* __restrict__ x,  const float* __restrict__ qw,
    const float* __restrict__ W1, const float* __restrict__ b1,
    const float* __restrict__ W2, const float* __restrict__ b2,
    const float* __restrict__ W3, const float* __restrict__ b3,
    float* __restrict__ out, int n)
{
    __shared__ __align__(16) float sw[SW_TOTAL];
    const int tid = threadIdx.x;

    for (int i = tid; i < 64;  i += BLK){ int k = i >> 4, j = i & 15; sw[OFF_W1 + i] = W1[j*4 + k]; }
    for (int i = tid; i < 512; i += BLK){ int k = i >> 5, j = i & 31; sw[OFF_W2 + i] = W2[j*16 + k]; }
    for (int i = tid; i < 512; i += BLK){ int k = i >> 4, j = i & 15; sw[OFF_W3 + i] = W3[j*32 + k]; }
    for (int i = tid; i < 16;  i += BLK) sw[OFF_B1 + i] = b1[i];
    for (int i = tid; i < 32;  i += BLK) sw[OFF_B2 + i] = b2[i];
    for (int i = tid; i < 16;  i += BLK) sw[OFF_B3 + i] = b3[i];
    if (tid == 0) {
        // Heisenberg coefficients: Z_i conjugated back through CNOT2 / RY(var) / CNOT1.
        // (Variational RZ is diagonal unit-phase -> vanishes under |.|^2.)
        float c[4], s[4];
#pragma unroll
        for (int i = 0; i < 4; i++) __sincosf(qw[2*i], &s[i], &c[i]);  // FULL angle (Bloch rotation)
        float K[30];
        K[0]=+c[0];                 K[1]=-s[0];
        K[2]=+c[0]*c[1];            K[3]=-c[0]*s[1];
        K[4]=+s[0]*c[1];            K[5]=+s[0]*s[1];
        K[6]=+c[0]*c[1]*c[2];       K[7]=-c[0]*c[1]*s[2];
        K[8]=+c[0]*s[1]*c[2];       K[9]=+c[0]*s[1]*s[2];
        K[10]=-s[0]*c[1]*c[2];      K[11]=-s[0]*c[1]*s[2];
        K[12]=-s[0]*s[1]*c[2];      K[13]=-s[0]*s[1]*s[2];
        K[14]=+c[0]*c[1]*c[2]*c[3]; K[15]=-c[0]*c[1]*c[2]*s[3];
        K[16]=+c[0]*c[1]*s[2]*c[3]; K[17]=+c[0]*c[1]*s[2]*s[3];
        K[18]=-c[0]*s[1]*c[2]*c[3]; K[19]=-c[0]*s[1]*c[2]*s[3];
        K[20]=-c[0]*s[1]*s[2]*c[3]; K[21]=-c[0]*s[1]*s[2]*s[3];
        K[22]=+s[0]*c[1]*c[2]*c[3]; K[23]=+s[0]*c[1]*c[2]*s[3];
        K[24]=-s[0]*c[1]*s[2]*c[3]; K[25]=+s[0]*c[1]*s[2]*s[3];
        K[26]=+s[0]*s[1]*c[2]*c[3]; K[27]=+s[0]*s[1]*c[2]*s[3];
        K[28]=+s[0]*s[1]*s[2]*c[3]; K[29]=+s[0]*s[1]*s[2]*s[3];
#pragma unroll
        for (int i = 0; i < 30; i++){ sw[OFF_C + 2*i] = K[i]; sw[OFF_C + 2*i + 1] = K[i]; }
    }
    __syncthreads();

    const int half = n >> 1;                   // pair (b, b+half)
    const int b0 = blockIdx.x * BLK + tid;
    if (b0 >= half) return;
    const int b1i = b0 + half;

    // ---- load x rows for both elements ----
    const float4* xv0 = (const float4*)(x + (size_t)b0  * 16);
    const float4* xv1 = (const float4*)(x + (size_t)b1i * 16);
    float4 q0 = xv0[0], q1 = xv0[1];
    float4 r0 = xv1[0], r1 = xv1[1];
    float xA[8] = {q0.x, q0.y, q0.z, q0.w, q1.x, q1.y, q1.z, q1.w};
    float xB[8] = {r0.x, r0.y, r0.z, r0.w, r1.x, r1.y, r1.z, r1.w};

    // ---- Bloch vectors of the input product state (batch-pair packed) ----
    // z = cos(pi*x_j), x = sin(pi*x_j)cos(pi*x_{j+4}), y = sin(pi*x_j)sin(pi*x_{j+4})
    P bz[4], bx[4], by[4];
#pragma unroll
    for (int i = 0; i < 4; i++) {
        float sA, cA, sB, cB, pA, qA, pB, qB;
        __sincosf(xA[i] * PI_F, &sA, &cA);
        __sincosf(xB[i] * PI_F, &sB, &cB);
        __sincosf(xA[i+4] * PI_F, &pA, &qA);
        __sincosf(xB[i+4] * PI_F, &pB, &qB);
        bz[i] = pack2(cA, cB);
        P sp = pack2(sA, sB);
        bx[i] = mul2(sp, pack2(qA, qB));
        by[i] = mul2(sp, pack2(pA, pB));
    }

    // ---- 30-term Pauli-string evaluation ----
    const P* Kp = (const P*)(sw + OFF_C);

    P a_ = mul2(bx[0], bx[1]);   // x0x1
    P b_ = mul2(bx[1], bx[2]);   // x1x2
    P c_ = mul2(bx[0], bx[2]);   // x0x2
    P d_ = mul2(by[0], by[1]);   // y0y1
    P e_ = mul2(by[1], by[2]);   // y1y2
    P f_ = mul2(bx[2], bx[3]);   // x2x3
    P h_ = mul2(bx[0], bx[3]);   // x0x3
    P i_ = mul2(bz[0], bz[2]);   // z0z2
    P j_ = mul2(by[2], by[3]);   // y2y3
    P k_ = mul2(bz[1], bz[3]);   // z1z3
    P l_ = mul2(bz[0], bx[1]);   // z0x1
    P m_ = mul2(by[0], bz[1]);   // y0z1
    P u_ = mul2(bz[0], b_);      // z0x1x2
    P v_ = mul2(a_, bz[2]);      // x0x1z2
    P w_ = mul2(m_, by[2]);      // y0z1y2

    P e0 = fma2(Kp[1], a_, mul2(Kp[0], bz[0]));

    P e1 = fma2(Kp[3], u_, mul2(Kp[2], bz[1]));
    e1 = fma2(Kp[4], d_, e1);
    e1 = fma2(Kp[5], c_, e1);

    P e2 = mul2(Kp[6], i_);
    e2 = fma2(Kp[7],  mul2(bz[1], f_), e2);
    e2 = fma2(Kp[8],  e_, e2);
    e2 = fma2(Kp[9],  mul2(l_, bx[3]), e2);
    e2 = fma2(Kp[10], v_, e2);
    e2 = fma2(Kp[11], mul2(d_, f_), e2);
    e2 = fma2(Kp[12], w_, e2);
    e2 = fma2(Kp[13], h_, e2);

    P e3 = mul2(Kp[14], k_);
    e3 = fma2(Kp[15], mul2(i_, bx[3]), e3);
    e3 = fma2(Kp[16], mul2(bz[0], j_), e3);
    e3 = fma2(Kp[17], mul2(bz[1], bx[2]), e3);
    e3 = fma2(Kp[18], mul2(u_, bz[3]), e3);
    e3 = fma2(Kp[19], mul2(e_, bx[3]), e3);
    e3 = fma2(Kp[20], mul2(mul2(by[1], bz[2]), by[3]), e3);
    e3 = fma2(Kp[21], l_, e3);
    e3 = fma2(Kp[22], mul2(d_, bz[3]), e3);
    e3 = fma2(Kp[23], mul2(v_, bx[3]), e3);
    e3 = fma2(Kp[24], mul2(a_, j_), e3);
    e3 = fma2(Kp[25], mul2(d_, bx[2]), e3);
    e3 = fma2(Kp[26], mul2(c_, bz[3]), e3);
    e3 = fma2(Kp[27], mul2(w_, bx[3]), e3);
    e3 = fma2(Kp[28], mul2(mul2(m_, bz[2]), by[3]), e3);
    e3 = fma2(Kp[29], bx[0], e3);

    float zA[4], zB[4];
    unpack2(e0, zA[0], zB[0]);
    unpack2(e1, zA[1], zB[1]);
    unpack2(e2, zA[2], zB[2]);
    unpack2(e3, zA[3], zB[3]);

    // ================= MLP: neuron-pair packing, weight loads shared A/B =================
    const P* B1p = (const P*)(sw + OFF_B1);
    const P* B2p = (const P*)(sw + OFF_B2);
    const P* B3p = (const P*)(sw + OFF_B3);

    // ---- layer 1: 4 -> 16 ----
    P aA1[8], aB1[8];
#pragma unroll
    for (int jp = 0; jp < 8; jp++) { P bb = B1p[jp]; aA1[jp] = bb; aB1[jp] = bb; }
#pragma unroll
    for (int k = 0; k < 4; k++) {
        P dA = dupP(zA[k]), dB = dupP(zB[k]);
        const ulonglong2* row = (const ulonglong2*)(sw + OFF_W1 + k*16);
#pragma unroll
        for (int q = 0; q < 4; q++) {
            ulonglong2 u = row[q];
            P w0 = mkP(u.x), w1 = mkP(u.y);
            aA1[2*q]   = fma2(w0, dA, aA1[2*q]);
            aA1[2*q+1] = fma2(w1, dA, aA1[2*q+1]);
            aB1[2*q]   = fma2(w0, dB, aB1[2*q]);
            aB1[2*q+1] = fma2(w1, dB, aB1[2*q+1]);
        }
    }
    float h1A[16], h1B[16];
#pragma unroll
    for (int jp = 0; jp < 8; jp++) {
        float lo, hi;
        unpack2(aA1[jp], lo, hi);
        h1A[2*jp] = fmaxf(lo, 0.0f); h1A[2*jp+1] = fmaxf(hi, 0.0f);
        unpack2(aB1[jp], lo, hi);
        h1B[2*jp] = fmaxf(lo, 0.0f); h1B[2*jp+1] = fmaxf(hi, 0.0f);
    }

    // ---- layer 2: 16 -> 32 ----
    P aA2[16], aB2[16];
#pragma unroll
    for (int jp = 0; jp < 16; jp++) { P bb = B2p[jp]; aA2[jp] = bb; aB2[jp] = bb; }
#pragma unroll
    for (int k = 0; k < 16; k++) {
        P dA = dupP(h1A[k]), dB = dupP(h1B[k]);
        const ulonglong2* row = (const ulonglong2*)(sw + OFF_W2 + k*32);
#pragma unroll
        for (int q = 0; q < 8; q++) {
            ulonglong2 u = row[q];
            P w0 = mkP(u.x), w1 = mkP(u.y);
            aA2[2*q]   = fma2(w0, dA, aA2[2*q]);
            aA2[2*q+1] = fma2(w1, dA, aA2[2*q+1]);
            aB2[2*q]   = fma2(w0, dB, aB2[2*q]);
            aB2[2*q+1] = fma2(w1, dB, aB2[2*q+1]);
        }
    }
    float h2A[32], h2B[32];
#pragma unroll
    for (int jp = 0; jp < 16; jp++) {
        float lo, hi;
        unpack2(aA2[jp], lo, hi);
        h2A[2*jp] = fmaxf(lo, 0.0f); h2A[2*jp+1] = fmaxf(hi, 0.0f);
        unpack2(aB2[jp], lo, hi);
        h2B[2*jp] = fmaxf(lo, 0.0f); h2B[2*jp+1] = fmaxf(hi, 0.0f);
    }

    // ---- layer 3: 32 -> 16 ----
    P aA3[8], aB3[8];
#pragma unroll
    for (int jp = 0; jp < 8; jp++) { P bb = B3p[jp]; aA3[jp] = bb; aB3[jp] = bb; }
#pragma unroll
    for (int k = 0; k < 32; k++) {
        P dA = dupP(h2A[k]), dB = dupP(h2B[k]);
        const ulonglong2* row = (const ulonglong2*)(sw + OFF_W3 + k*16);
#pragma unroll
        for (int q = 0; q < 4; q++) {
            ulonglong2 u = row[q];
            P w0 = mkP(u.x), w1 = mkP(u.y);
            aA3[2*q]   = fma2(w0, dA, aA3[2*q]);
            aA3[2*q+1] = fma2(w1, dA, aA3[2*q+1]);
            aB3[2*q]   = fma2(w0, dB, aB3[2*q]);
            aB3[2*q+1] = fma2(w1, dB, aB3[2*q+1]);
        }
    }

    // ---- store: acc pairs are already {o_2j, o_2j+1} in memory order ----
    float* o0 = out + (size_t)b0  * 16;
    float* o1 = out + (size_t)b1i * 16;
#pragma unroll
    for (int g = 0; g < 4; g++) {
        float4 v;
        unpack2(aA3[2*g],   v.x, v.y);
        unpack2(aA3[2*g+1], v.z, v.w);
        ((float4*)o0)[g] = v;
        unpack2(aB3[2*g],   v.x, v.y);
        unpack2(aB3[2*g+1], v.z, v.w);
        ((float4*)o1)[g] = v;
    }
}

extern "C" void kernel_launch(void* const* d_in, const int* in_sizes, int n_in,
                              void* d_out, int out_size)
{
    const float* x  = (const float*)d_in[0];
    const float* qw = (const float*)d_in[1];
    const float* W1 = (const float*)d_in[2];
    const float* b1 = (const float*)d_in[3];
    const float* W2 = (const float*)d_in[4];
    const float* b2 = (const float*)d_in[5];
    const float* W3 = (const float*)d_in[6];
    const float* b3 = (const float*)d_in[7];
    float* out = (float*)d_out;

    const int n = in_sizes[0] / 16;           // B (even)
    const int half = n >> 1;
    const int blocks = (half + BLK - 1) / BLK;
    hqae_kernel<<<blocks, BLK>>>(x, qw, W1, b1, W2, b2, W3, b3, out, n);
}

// round 9
// speedup vs baseline: 1.2792x; 1.0315x over previous
#include <cuda_runtime.h>

#define PI_F 3.14159265358979f

typedef unsigned long long u64;
struct P { u64 v; };

__device__ __forceinline__ P mkP(u64 x){ P r; r.v = x; return r; }
__device__ __forceinline__ P pack2(float lo, float hi){
    P r; asm("mov.b64 %0,{%1,%2};" : "=l"(r.v) : "f"(lo), "f"(hi)); return r;
}
__device__ __forceinline__ P dupP(float v){
    P r; asm("mov.b64 %0,{%1,%1};" : "=l"(r.v) : "f"(v)); return r;
}
__device__ __forceinline__ void unpack2(P a, float& lo, float& hi){
    asm("mov.b64 {%0,%1},%2;" : "=f"(lo), "=f"(hi) : "l"(a.v));
}
__device__ __forceinline__ P fma2(P a, P b, P c){
    P r; asm("fma.rn.f32x2 %0,%1,%2,%3;" : "=l"(r.v) : "l"(a.v), "l"(b.v), "l"(c.v)); return r;
}
#define K_ZERO (mkP(0ULL))
__device__ __forceinline__ P mul2(P a, P b){ return fma2(a, b, K_ZERO); }

// shared layout (floats). MLP weights TRANSPOSED, adjacent-neuron pairs.
#define OFF_W1   0      // 64
#define OFF_B1   64     // 16
#define OFF_W2   80     // 512
#define OFF_B2   592    // 32
#define OFF_W3   624    // 512
#define OFF_B3   1136   // 16
#define OFF_C    1152   // 60 (30 pair-duplicated Heisenberg coefficients)
#define SW_TOTAL 1216

#define BLK 160

__global__ __launch_bounds__(BLK, 4) void hqae_kernel(
    const float* __restrict__ x,  const float* __restrict__ qw,
    const float* __restrict__ W1, const float* __restrict__ b1,
    const float* __restrict__ W2, const float* __restrict__ b2,
    const float* __restrict__ W3, const float* __restrict__ b3,
    float* __restrict__ out, int n)
{
    __shared__ __align__(16) float sw[SW_TOTAL];
    const int tid = threadIdx.x;

    for (int i = tid; i < 64;  i += BLK){ int k = i >> 4, j = i & 15; sw[OFF_W1 + i] = W1[j*4 + k]; }
    for (int i = tid; i < 512; i += BLK){ int k = i >> 5, j = i & 31; sw[OFF_W2 + i] = W2[j*16 + k]; }
    for (int i = tid; i < 512; i += BLK){ int k = i >> 4, j = i & 15; sw[OFF_W3 + i] = W3[j*32 + k]; }
    for (int i = tid; i < 16;  i += BLK) sw[OFF_B1 + i] = b1[i];
    for (int i = tid; i < 32;  i += BLK) sw[OFF_B2 + i] = b2[i];
    for (int i = tid; i < 16;  i += BLK) sw[OFF_B3 + i] = b3[i];
    if (tid == 0) {
        // Heisenberg coefficients: Z_i conjugated back through CNOT2 / RY(var) / CNOT1.
        // (Variational RZ is diagonal unit-phase -> vanishes under |.|^2.)
        float c[4], s[4];
#pragma unroll
        for (int i = 0; i < 4; i++) __sincosf(qw[2*i], &s[i], &c[i]);  // FULL angle (Bloch rotation)
        float K[30];
        K[0]=+c[0];                 K[1]=-s[0];
        K[2]=+c[0]*c[1];            K[3]=-c[0]*s[1];
        K[4]=+s[0]*c[1];            K[5]=+s[0]*s[1];
        K[6]=+c[0]*c[1]*c[2];       K[7]=-c[0]*c[1]*s[2];
        K[8]=+c[0]*s[1]*c[2];       K[9]=+c[0]*s[1]*s[2];
        K[10]=-s[0]*c[1]*c[2];      K[11]=-s[0]*c[1]*s[2];
        K[12]=-s[0]*s[1]*c[2];      K[13]=-s[0]*s[1]*s[2];
        K[14]=+c[0]*c[1]*c[2]*c[3]; K[15]=-c[0]*c[1]*c[2]*s[3];
        K[16]=+c[0]*c[1]*s[2]*c[3]; K[17]=+c[0]*c[1]*s[2]*s[3];
        K[18]=-c[0]*s[1]*c[2]*c[3]; K[19]=-c[0]*s[1]*c[2]*s[3];
        K[20]=-c[0]*s[1]*s[2]*c[3]; K[21]=-c[0]*s[1]*s[2]*s[3];
        K[22]=+s[0]*c[1]*c[2]*c[3]; K[23]=+s[0]*c[1]*c[2]*s[3];
        K[24]=-s[0]*c[1]*s[2]*c[3]; K[25]=+s[0]*c[1]*s[2]*s[3];
        K[26]=+s[0]*s[1]*c[2]*c[3]; K[27]=+s[0]*s[1]*c[2]*s[3];
        K[28]=+s[0]*s[1]*s[2]*c[3]; K[29]=+s[0]*s[1]*s[2]*s[3];
#pragma unroll
        for (int i = 0; i < 30; i++){ sw[OFF_C + 2*i] = K[i]; sw[OFF_C + 2*i + 1] = K[i]; }
    }
    __syncthreads();

    const int half = n >> 1;                   // pair (b, b+half)
    const int b0 = blockIdx.x * BLK + tid;
    if (b0 >= half) return;
    const int b1i = b0 + half;

    // ---- load x rows for both elements ----
    const float4* xv0 = (const float4*)(x + (size_t)b0  * 16);
    const float4* xv1 = (const float4*)(x + (size_t)b1i * 16);
    float4 q0 = xv0[0], q1 = xv0[1];
    float4 r0 = xv1[0], r1 = xv1[1];
    float xA[8] = {q0.x, q0.y, q0.z, q0.w, q1.x, q1.y, q1.z, q1.w};
    float xB[8] = {r0.x, r0.y, r0.z, r0.w, r1.x, r1.y, r1.z, r1.w};

    // ---- Bloch vectors of the input product state (batch-pair packed) ----
    P bz[4], bx[4], by[4];
#pragma unroll
    for (int i = 0; i < 4; i++) {
        float sA, cA, sB, cB, pA, qA, pB, qB;
        __sincosf(xA[i] * PI_F, &sA, &cA);
        __sincosf(xB[i] * PI_F, &sB, &cB);
        __sincosf(xA[i+4] * PI_F, &pA, &qA);
        __sincosf(xB[i+4] * PI_F, &pB, &qB);
        bz[i] = pack2(cA, cB);
        P sp = pack2(sA, sB);
        bx[i] = mul2(sp, pack2(qA, qB));
        by[i] = mul2(sp, pack2(pA, pB));
    }

    // ---- 30-term Pauli-string evaluation ----
    const P* Kp = (const P*)(sw + OFF_C);

    P a_ = mul2(bx[0], bx[1]);   // x0x1
    P b_ = mul2(bx[1], bx[2]);   // x1x2
    P c_ = mul2(bx[0], bx[2]);   // x0x2
    P d_ = mul2(by[0], by[1]);   // y0y1
    P e_ = mul2(by[1], by[2]);   // y1y2
    P f_ = mul2(bx[2], bx[3]);   // x2x3
    P h_ = mul2(bx[0], bx[3]);   // x0x3
    P i_ = mul2(bz[0], bz[2]);   // z0z2
    P j_ = mul2(by[2], by[3]);   // y2y3
    P k_ = mul2(bz[1], bz[3]);   // z1z3
    P l_ = mul2(bz[0], bx[1]);   // z0x1
    P m_ = mul2(by[0], bz[1]);   // y0z1
    P u_ = mul2(bz[0], b_);      // z0x1x2
    P v_ = mul2(a_, bz[2]);      // x0x1z2
    P w_ = mul2(m_, by[2]);      // y0z1y2

    P e0 = fma2(Kp[1], a_, mul2(Kp[0], bz[0]));

    P e1 = fma2(Kp[3], u_, mul2(Kp[2], bz[1]));
    e1 = fma2(Kp[4], d_, e1);
    e1 = fma2(Kp[5], c_, e1);

    P e2 = mul2(Kp[6], i_);
    e2 = fma2(Kp[7],  mul2(bz[1], f_), e2);
    e2 = fma2(Kp[8],  e_, e2);
    e2 = fma2(Kp[9],  mul2(l_, bx[3]), e2);
    e2 = fma2(Kp[10], v_, e2);
    e2 = fma2(Kp[11], mul2(d_, f_), e2);
    e2 = fma2(Kp[12], w_, e2);
    e2 = fma2(Kp[13], h_, e2);

    P e3 = mul2(Kp[14], k_);
    e3 = fma2(Kp[15], mul2(i_, bx[3]), e3);
    e3 = fma2(Kp[16], mul2(bz[0], j_), e3);
    e3 = fma2(Kp[17], mul2(bz[1], bx[2]), e3);
    e3 = fma2(Kp[18], mul2(u_, bz[3]), e3);
    e3 = fma2(Kp[19], mul2(e_, bx[3]), e3);
    e3 = fma2(Kp[20], mul2(mul2(by[1], bz[2]), by[3]), e3);
    e3 = fma2(Kp[21], l_, e3);
    e3 = fma2(Kp[22], mul2(d_, bz[3]), e3);
    e3 = fma2(Kp[23], mul2(v_, bx[3]), e3);
    e3 = fma2(Kp[24], mul2(a_, j_), e3);
    e3 = fma2(Kp[25], mul2(d_, bx[2]), e3);
    e3 = fma2(Kp[26], mul2(c_, bz[3]), e3);
    e3 = fma2(Kp[27], mul2(w_, bx[3]), e3);
    e3 = fma2(Kp[28], mul2(mul2(m_, bz[2]), by[3]), e3);
    e3 = fma2(Kp[29], bx[0], e3);

    float zA[4], zB[4];
    unpack2(e0, zA[0], zB[0]);
    unpack2(e1, zA[1], zB[1]);
    unpack2(e2, zA[2], zB[2]);
    unpack2(e3, zA[3], zB[3]);

    // ================= MLP: neuron-pair packing, chunked k-loops for low reg pressure ====
    const P* B1p = (const P*)(sw + OFF_B1);
    const P* B2p = (const P*)(sw + OFF_B2);
    const P* B3p = (const P*)(sw + OFF_B3);

    // ---- layer 1: 4 -> 16 (unchunked; accs 16P) ----
    float h1A[16], h1B[16];
    {
        P aA[8], aB[8];
#pragma unroll
        for (int jp = 0; jp < 8; jp++) { P bb = B1p[jp]; aA[jp] = bb; aB[jp] = bb; }
#pragma unroll
        for (int k = 0; k < 4; k++) {
            P dA = dupP(zA[k]), dB = dupP(zB[k]);
            const ulonglong2* row = (const ulonglong2*)(sw + OFF_W1 + k*16);
#pragma unroll
            for (int q = 0; q < 4; q++) {
                ulonglong2 u = row[q];
                P w0 = mkP(u.x), w1 = mkP(u.y);
                aA[2*q]   = fma2(w0, dA, aA[2*q]);
                aA[2*q+1] = fma2(w1, dA, aA[2*q+1]);
                aB[2*q]   = fma2(w0, dB, aB[2*q]);
                aB[2*q+1] = fma2(w1, dB, aB[2*q+1]);
            }
        }
#pragma unroll
        for (int jp = 0; jp < 8; jp++) {
            float lo, hi;
            unpack2(aA[jp], lo, hi);
            h1A[2*jp] = fmaxf(lo, 0.0f); h1A[2*jp+1] = fmaxf(hi, 0.0f);
            unpack2(aB[jp], lo, hi);
            h1B[2*jp] = fmaxf(lo, 0.0f); h1B[2*jp+1] = fmaxf(hi, 0.0f);
        }
    }

    // ---- layer 2: 16 -> 32, in 4 chunks of 8 neurons (accs only 8P live) ----
    float h2A[32], h2B[32];
#pragma unroll
    for (int c = 0; c < 4; c++) {
        P aA[4], aB[4];
#pragma unroll
        for (int jp = 0; jp < 4; jp++) { P bb = B2p[c*4 + jp]; aA[jp] = bb; aB[jp] = bb; }
#pragma unroll
        for (int k = 0; k < 16; k++) {
            P dA = dupP(h1A[k]), dB = dupP(h1B[k]);
            const ulonglong2* row = (const ulonglong2*)(sw + OFF_W2 + k*32 + c*8);
#pragma unroll
            for (int q = 0; q < 2; q++) {
                ulonglong2 u = row[q];
                P w0 = mkP(u.x), w1 = mkP(u.y);
                aA[2*q]   = fma2(w0, dA, aA[2*q]);
                aA[2*q+1] = fma2(w1, dA, aA[2*q+1]);
                aB[2*q]   = fma2(w0, dB, aB[2*q]);
                aB[2*q+1] = fma2(w1, dB, aB[2*q+1]);
            }
        }
#pragma unroll
        for (int jp = 0; jp < 4; jp++) {
            float lo, hi;
            unpack2(aA[jp], lo, hi);
            h2A[c*8 + 2*jp] = fmaxf(lo, 0.0f); h2A[c*8 + 2*jp+1] = fmaxf(hi, 0.0f);
            unpack2(aB[jp], lo, hi);
            h2B[c*8 + 2*jp] = fmaxf(lo, 0.0f); h2B[c*8 + 2*jp+1] = fmaxf(hi, 0.0f);
        }
    }

    // ---- layer 3: 32 -> 16, in 2 chunks of 8 neurons; store per chunk ----
    float* o0 = out + (size_t)b0  * 16;
    float* o1 = out + (size_t)b1i * 16;
#pragma unroll
    for (int c = 0; c < 2; c++) {
        P aA[4], aB[4];
#pragma unroll
        for (int jp = 0; jp < 4; jp++) { P bb = B3p[c*4 + jp]; aA[jp] = bb; aB[jp] = bb; }
#pragma unroll
        for (int k = 0; k < 32; k++) {
            P dA = dupP(h2A[k]), dB = dupP(h2B[k]);
            const ulonglong2* row = (const ulonglong2*)(sw + OFF_W3 + k*16 + c*8);
#pragma unroll
            for (int q = 0; q < 2; q++) {
                ulonglong2 u = row[q];
                P w0 = mkP(u.x), w1 = mkP(u.y);
                aA[2*q]   = fma2(w0, dA, aA[2*q]);
                aA[2*q+1] = fma2(w1, dA, aA[2*q+1]);
                aB[2*q]   = fma2(w0, dB, aB[2*q]);
                aB[2*q+1] = fma2(w1, dB, aB[2*q+1]);
            }
        }
        float4 v;
        unpack2(aA[0], v.x, v.y); unpack2(aA[1], v.z, v.w);
        ((float4*)o0)[c*2]     = v;
        unpack2(aA[2], v.x, v.y); unpack2(aA[3], v.z, v.w);
        ((float4*)o0)[c*2 + 1] = v;
        unpack2(aB[0], v.x, v.y); unpack2(aB[1], v.z, v.w);
        ((float4*)o1)[c*2]     = v;
        unpack2(aB[2], v.x, v.y); unpack2(aB[3], v.z, v.w);
        ((float4*)o1)[c*2 + 1] = v;
    }
}

extern "C" void kernel_launch(void* const* d_in, const int* in_sizes, int n_in,
                              void* d_out, int out_size)
{
    const float* x  = (const float*)d_in[0];
    const float* qw = (const float*)d_in[1];
    const float* W1 = (const float*)d_in[2];
    const float* b1 = (const float*)d_in[3];
    const float* W2 = (const float*)d_in[4];
    const float* b2 = (const float*)d_in[5];
    const float* W3 = (const float*)d_in[6];
    const float* b3 = (const float*)d_in[7];
    float* out = (float*)d_out;

    const int n = in_sizes[0] / 16;           // B (even)
    const int half = n >> 1;
    const int blocks = (half + BLK - 1) / BLK;
    hqae_kernel<<<blocks, BLK>>>(x, qw, W1, b1, W2, b2, W3, b3, out, n);
}